// round 14
// baseline (speedup 1.0000x reference)
#include <cuda_runtime.h>
#include <cuda_fp16.h>
#include <cstdint>
#include <cstddef>

#define Bb 256
#define Tt 128
#define Dd 1024
#define Hh 1024
#define BTr (Bb*Tt)            // 32768
#define G3  (3*Hh)             // 3072
#define BTH ((size_t)BTr*Hh)

// ------------------------- device scratch (no mallocs) ----------------------
__device__ float g_gi[(size_t)BTr * G3];                  // 402 MB
__device__ float g_hseq_fallback[BTH];                    // 128 MB
__device__ int   g_mask_mode;
__device__ unsigned int g_flag[4][Tt][8];                 // per-chain dataflow flags
__device__ __align__(16) __half g_whh[(size_t)G3 * Hh];   // W_hh fp16
__device__ __align__(16) __half g_wih[(size_t)G3 * Dd];   // W_ih fp16
__device__ __align__(16) __half g_x[(size_t)BTr * Dd];    // x fp16
__device__ __align__(16) __half g_hh[2][(size_t)Bb * Hh]; // h ping-pong fp16

// ------------------------------ PTX helpers (base sm_103 safe) ---------------
__device__ __forceinline__ uint32_t smem_u32(const void* p) {
    uint32_t a;
    asm("{ .reg .u64 t; cvta.to.shared.u64 t, %1; cvt.u32.u64 %0, t; }"
        : "=r"(a) : "l"(p));
    return a;
}
__device__ __forceinline__ void cp16(uint32_t dst, const void* src) {
    asm volatile("cp.async.cg.shared.global [%0], [%1], 16;"
                 :: "r"(dst), "l"(src) : "memory");
}
#define CP_COMMIT() asm volatile("cp.async.commit_group;" ::: "memory")
#define CP_WAIT(n)  asm volatile("cp.async.wait_group %0;" :: "n"(n) : "memory")

__device__ __forceinline__ void ldsm_x4(uint32_t* r, uint32_t addr) {
    asm volatile("ldmatrix.sync.aligned.m8n8.x4.shared.b16 {%0,%1,%2,%3}, [%4];"
                 : "=r"(r[0]), "=r"(r[1]), "=r"(r[2]), "=r"(r[3]) : "r"(addr));
}
__device__ __forceinline__ void ldsm_x2(uint32_t* r, uint32_t addr) {
    asm volatile("ldmatrix.sync.aligned.m8n8.x2.shared.b16 {%0,%1}, [%2];"
                 : "=r"(r[0]), "=r"(r[1]) : "r"(addr));
}
__device__ __forceinline__ void mma16816h(float* d, const uint32_t* a, const uint32_t* b) {
    asm volatile("mma.sync.aligned.m16n8k16.row.col.f32.f16.f16.f32 "
                 "{%0,%1,%2,%3}, {%4,%5,%6,%7}, {%8,%9}, {%0,%1,%2,%3};"
                 : "+f"(d[0]), "+f"(d[1]), "+f"(d[2]), "+f"(d[3])
                 : "r"(a[0]), "r"(a[1]), "r"(a[2]), "r"(a[3]), "r"(b[0]), "r"(b[1]));
}
__device__ __forceinline__ uint32_t pack2h(__half a, __half b) {
    return ((uint32_t)__half_as_ushort(b) << 16) | __half_as_ushort(a);
}
__device__ __forceinline__ unsigned int ld_acq(const unsigned int* p) {
    unsigned int v;
    asm volatile("ld.acquire.gpu.global.u32 %0, [%1];" : "=r"(v) : "l"(p) : "memory");
    return v;
}
__device__ __forceinline__ void red_release(unsigned int* p, unsigned int v) {
    asm volatile("red.release.gpu.global.add.u32 [%0], %1;" :: "l"(p), "r"(v) : "memory");
}
__device__ __forceinline__ void wait_n(const unsigned int* f, unsigned int n) {
    while (ld_acq(f) < n) __nanosleep(40);
}

// --------------------------- mask dtype handling ------------------------------
__device__ __forceinline__ float mask_of(const void* p, int b, int t) {
    int idx = b * Tt + t;
    int mode = g_mask_mode;
    bool ii;
    if (mode == 2)      ii = ((const float*)p)[idx] != 0.0f;
    else if (mode == 1) ii = ((const unsigned char*)p)[idx] != 0;
    else                ii = ((const int*)p)[idx] != 0;
    return ii ? 0.0f : 1.0f;
}

// --------------------- prep: fp32 -> fp16 (+ folded housekeeping) ------------
__device__ __forceinline__ void to_h4(const float4* src, __half* dst, size_t i) {
    float4 v = src[i];
    ((uint2*)dst)[i] = make_uint2(pack2h(__float2half(v.x), __float2half(v.y)),
                                  pack2h(__float2half(v.z), __float2half(v.w)));
}
// prepA: W_hh [0,3072) + W_ih [3072,6144) + block 6144 = reset flags
__global__ void __launch_bounds__(256) prepA(const float* __restrict__ Whh,
                                             const float* __restrict__ Wih) {
    int b = blockIdx.x;
    if (b < 3072) to_h4((const float4*)Whh, g_whh, (size_t)b * 256 + threadIdx.x);
    else if (b < 6144) to_h4((const float4*)Wih, g_wih, (size_t)(b - 3072) * 256 + threadIdx.x);
    else {
        unsigned int* f = &g_flag[0][0][0];
        for (int i = threadIdx.x; i < 4 * Tt * 8; i += 256) f[i] = 0u;
    }
}
// prepB: x [0,32768) + hx [32768,33024) + block 33024 = detect mask dtype
__global__ void __launch_bounds__(256) prepB(const float* __restrict__ x,
                                             const float* __restrict__ hx,
                                             const unsigned char* __restrict__ isin) {
    int b = blockIdx.x;
    if (b < 32768) { to_h4((const float4*)x, g_x, (size_t)b * 256 + threadIdx.x); return; }
    if (b < 33024) {
        to_h4((const float4*)hx, g_hh[0], (size_t)(b - 32768) * 256 + threadIdx.x);
        return;
    }
    __shared__ int s_off, s_gt1;
    if (threadIdx.x == 0) { s_off = 0; s_gt1 = 0; }
    __syncthreads();
    int f_off = 0, f_gt1 = 0;
    for (int i = threadIdx.x; i < 4096; i += 256) {
        unsigned char v = isin[i];
        if ((i & 3) != 0 && v) f_off = 1;
        if (v > 1) f_gt1 = 1;
    }
    if (f_off) atomicOr(&s_off, 1);
    if (f_gt1) atomicOr(&s_gt1, 1);
    __syncthreads();
    if (threadIdx.x == 0) g_mask_mode = s_gt1 ? 2 : (s_off ? 1 : 0);
}

// ------- gi = x @ W_ih^T + b_ih  (fp16, KC=64, 3-stage, 1 sync/chunk) --------
#define GI_KC 64
#define GI_NCH 16
#define GI_PITCH 144
#define GI_AB (128 * GI_PITCH)          // 18432
#define GI_STAGE (2 * GI_AB)            // 36864
#define GI_SMEM (3 * GI_STAGE)          // 110592

__global__ void __launch_bounds__(256, 2) gi_gemm(const float* __restrict__ bias) {
    extern __shared__ char sm[];
    const uint32_t sb = smem_u32(sm);
    const int tid = threadIdx.x, lane = tid & 31, wid = tid >> 5;
    const int wm = wid >> 2, wn = wid & 3;
    const int n0 = blockIdx.x * 128, m0 = blockIdx.y * 128;

    float acc[4][4][4];
#pragma unroll
    for (int i = 0; i < 4; i++)
#pragma unroll
        for (int j = 0; j < 4; j++)
#pragma unroll
            for (int k = 0; k < 4; k++) acc[i][j][k] = 0.0f;

#define GI_ISSUE(ch) do {                                                        \
    const int _c = (ch);                                                         \
    const uint32_t base = sb + (_c % 3) * GI_STAGE;                              \
    _Pragma("unroll")                                                            \
    for (int it = 0; it < 4; it++) {                                             \
        int i = tid + it * 256, r = i >> 3, q = i & 7;                           \
        cp16(base + r * GI_PITCH + q * 16,                                       \
             g_x + (size_t)(m0 + r) * Dd + _c * GI_KC + q * 8);                  \
    }                                                                            \
    _Pragma("unroll")                                                            \
    for (int it = 0; it < 4; it++) {                                             \
        int i = tid + it * 256, r = i >> 3, q = i & 7;                           \
        cp16(base + GI_AB + r * GI_PITCH + q * 16,                               \
             g_wih + (size_t)(n0 + r) * Dd + _c * GI_KC + q * 8);                \
    }                                                                            \
    CP_COMMIT(); } while (0)

    const int bl_row = ((lane >> 4) << 3) + (lane & 7);
    const int bl_koff = ((lane >> 3) & 1) * 16;

    GI_ISSUE(0);
    GI_ISSUE(1);
    for (int ch = 0; ch < GI_NCH; ch++) {
        if (ch == GI_NCH - 1) { CP_WAIT(0); } else { CP_WAIT(1); }
        __syncthreads();
        if (ch + 2 < GI_NCH) GI_ISSUE(ch + 2);
        const uint32_t base = sb + (ch % 3) * GI_STAGE;
        const uint32_t aS = base, bS = base + GI_AB;
#pragma unroll
        for (int ks = 0; ks < 4; ks++) {
            uint32_t ah[4][4], bh[4][2];
#pragma unroll
            for (int ma = 0; ma < 4; ma++)
                ldsm_x4(ah[ma], aS + (wm * 64 + ma * 16 + (lane & 15)) * GI_PITCH
                                    + ks * 32 + (lane >> 4) * 16);
#pragma unroll
            for (int np = 0; np < 2; np++)
                ldsm_x4(&bh[np * 2][0],
                        bS + (wn * 32 + np * 16 + bl_row) * GI_PITCH
                           + ks * 32 + bl_koff);
#pragma unroll
            for (int ma = 0; ma < 4; ma++)
#pragma unroll
                for (int na = 0; na < 4; na++) mma16816h(acc[ma][na], ah[ma], bh[na]);
        }
    }
#pragma unroll
    for (int ma = 0; ma < 4; ma++) {
        const int row = m0 + wm * 64 + ma * 16 + (lane >> 2);
#pragma unroll
        for (int na = 0; na < 4; na++) {
            const int col = n0 + wn * 32 + na * 8 + (lane & 3) * 2;
            const float b0 = bias[col], b1 = bias[col + 1];
            float* p = g_gi + (size_t)row * G3 + col;
            *(float2*)p = make_float2(acc[ma][na][0] + b0, acc[ma][na][1] + b1);
            *(float2*)(p + 8 * (size_t)G3) =
                make_float2(acc[ma][na][2] + b0, acc[ma][na][3] + b1);
        }
    }
}

// ---- persistent scan: TWO independent 64-row chains per block (latency hide) -
// 4 batch chains of 64 rows. Grid (64,2): block (cx,gy) runs chains 2gy,2gy+1
// at cols [16cx,16cx+16), alternating per step so one chain's compute hides the
// other's cross-block hand-off. W slice (48x1024) resident, shared by chains.
#define KC 128
#define NCH 8
#define A_PITCH 272                         // 128 fp16 + 16 pad
#define A_BUF64 (64 * A_PITCH)              // 17408
#define SM_W (3 * A_BUF64)                  // 52224
#define W_PITCH 2064
#define W_PART (48 * W_PITCH)               // 99072
#define SM_MASK (SM_W + W_PART)             // 151296
#define PS_SMEM (SM_MASK + 384)             // 151680

#define PS_ISSUE_A64(cc, hin, m0v) do {                                          \
    const uint32_t base = sb + ((cc) % 3) * A_BUF64;                             \
    _Pragma("unroll")                                                            \
    for (int it = 0; it < 4; it++) {                                             \
        int i = tid + it * 256, r = i >> 4, q = i & 15;                          \
        cp16(base + r * A_PITCH + q * 16,                                        \
             (hin) + (size_t)((m0v) + r) * Hh + (cc) * KC + q * 8);              \
    }                                                                            \
    CP_COMMIT(); } while (0)

__device__ __forceinline__ void chain_step(
    int t, int chain, int m0, int cx, int c0,
    uint32_t sb, float* maskS,
    const __half* __restrict__ hin, __half* __restrict__ hout,
    float* __restrict__ Hseq, const void* __restrict__ isin,
    const float* br_, const float* bz_, const float* bn_,
    float (&hreg)[2][2],
    int tid, int lane, int wm, int wn, int ccl0, int bl_row, int bl_koff)
{
    // gi registers (h-independent): load before any dataflow wait
    float2 gir[3][2];
#pragma unroll
    for (int rh = 0; rh < 2; rh++) {
        const size_t rbase =
            ((size_t)(m0 + wm * 16 + (lane >> 2) + rh * 8) * Tt + t) * G3 + c0 + ccl0;
#pragma unroll
        for (int g = 0; g < 3; g++)
            gir[g][rh] = *(const float2*)(g_gi + rbase + g * Hh);
    }
    if (tid < 64) maskS[tid] = mask_of(isin, m0 + tid, t);

    // prologue: chunks 0,1
    if (t > 0) wait_n(&g_flag[chain][t - 1][0], 8);
    PS_ISSUE_A64(0, hin, m0);
    if (t > 0) wait_n(&g_flag[chain][t - 1][1], 8);
    PS_ISSUE_A64(1, hin, m0);

    float acc[3][4];
#pragma unroll
    for (int j = 0; j < 3; j++)
#pragma unroll
        for (int k = 0; k < 4; k++) acc[j][k] = 0.0f;

    for (int ch = 0; ch < NCH; ch++) {
        if (ch == NCH - 1) { CP_WAIT(0); } else { CP_WAIT(1); }
        __syncthreads();
        if (ch + 2 < NCH) {
            if (t > 0) wait_n(&g_flag[chain][t - 1][ch + 2], 8);
            PS_ISSUE_A64(ch + 2, hin, m0);
        }
        const uint32_t abase = sb + (ch % 3) * A_BUF64;
        const uint32_t wS = sb + SM_W + ch * 256;
#pragma unroll
        for (int ks = 0; ks < 8; ks++) {
            uint32_t ah[4], bh[3][2];
            ldsm_x4(ah, abase + (wm * 16 + (lane & 15)) * A_PITCH
                              + ks * 32 + (lane >> 4) * 16);
            ldsm_x4(&bh[0][0], wS + (wn * 24 + bl_row) * W_PITCH
                                  + ks * 32 + bl_koff);
            {
                int l = lane & 15;
                ldsm_x2(bh[2], wS + (wn * 24 + 16 + (l & 7)) * W_PITCH
                                  + ks * 32 + (l >> 3) * 16);
            }
#pragma unroll
            for (int na = 0; na < 3; na++) mma16816h(acc[na], ah, bh[na]);
        }
    }

    // register epilogue (na == gate)
#pragma unroll
    for (int rh = 0; rh < 2; rh++) {
        const int lr = wm * 16 + (lane >> 2) + rh * 8;
        const int brow = m0 + lr;
        const float m = maskS[lr];
        float hv[2];
#pragma unroll
        for (int j = 0; j < 2; j++) {
            const int k = rh * 2 + j;
            const float hrv = m * acc[0][k] + br_[j];
            const float hzv = m * acc[1][k] + bz_[j];
            const float hnv = m * acc[2][k] + bn_[j];
            const float ir  = j ? gir[0][rh].y : gir[0][rh].x;
            const float iz  = j ? gir[1][rh].y : gir[1][rh].x;
            const float inn = j ? gir[2][rh].y : gir[2][rh].x;
            const float rg = 1.0f / (1.0f + __expf(-(ir + hrv)));
            const float z  = 1.0f / (1.0f + __expf(-(iz + hzv)));
            const float n  = tanhf(inn + rg * hnv);
            hv[j] = (1.0f - z) * n + z * (hreg[rh][j] * m);
            hreg[rh][j] = hv[j];
        }
        *(float2*)(Hseq + ((size_t)brow * Tt + t) * Hh + c0 + ccl0) =
            make_float2(hv[0], hv[1]);
        *(uint32_t*)(hout + (size_t)brow * Hh + c0 + ccl0) =
            pack2h(__float2half(hv[0]), __float2half(hv[1]));
    }
    __syncthreads();     // orders epilogue stores before release; guards maskS/stages
    if (tid == 0 && t + 1 < Tt) red_release(&g_flag[chain][t][cx >> 3], 1u);
}

__global__ void __launch_bounds__(256)
scan_all(const float* __restrict__ bhh, const float* __restrict__ hx,
         const void* __restrict__ isin, float* __restrict__ Hseq) {
    extern __shared__ char sm[];
    const uint32_t sb = smem_u32(sm);
    float* maskS = (float*)(sm + SM_MASK);
    const int tid = threadIdx.x, lane = tid & 31, wid = tid >> 5;
    const int wm = wid >> 1, wn = wid & 1;           // 4 x 2 warps, tile 16x24
    const int cx = blockIdx.x, gy = blockIdx.y;
    const int c0 = cx * 16;
    const int ca = gy * 2, cb = ca + 1;
    const int m0a = ca * 64, m0b = cb * 64;

    // one-time: load W slice into resident smem (remapped rows)
#pragma unroll 8
    for (int it = 0; it < 24; it++) {
        int i = tid + it * 256;
        int rs = i >> 7, q = i & 127;
        int g = rs >> 4, ccl = rs & 15;
        int rr = (ccl >> 3) * 24 + g * 8 + (ccl & 7);
        cp16(sb + SM_W + rr * W_PITCH + q * 16,
             g_whh + (size_t)(g * Hh + c0 + ccl) * Hh + q * 8);
    }
    CP_COMMIT();

    const int ccl0 = wn * 8 + (lane & 3) * 2;
    const int bl_row = ((lane >> 4) << 3) + (lane & 7);
    const int bl_koff = ((lane >> 3) & 1) * 16;
    float br_[2], bz_[2], bn_[2];
#pragma unroll
    for (int j = 0; j < 2; j++) {
        br_[j] = bhh[c0 + ccl0 + j];
        bz_[j] = bhh[Hh + c0 + ccl0 + j];
        bn_[j] = bhh[2 * Hh + c0 + ccl0 + j];
    }
    float hregA[2][2], hregB[2][2];
#pragma unroll
    for (int rh = 0; rh < 2; rh++) {
        const int lr = wm * 16 + (lane >> 2) + rh * 8;
        hregA[rh][0] = hx[(size_t)(m0a + lr) * Hh + c0 + ccl0];
        hregA[rh][1] = hx[(size_t)(m0a + lr) * Hh + c0 + ccl0 + 1];
        hregB[rh][0] = hx[(size_t)(m0b + lr) * Hh + c0 + ccl0];
        hregB[rh][1] = hx[(size_t)(m0b + lr) * Hh + c0 + ccl0 + 1];
    }

    for (int t = 0; t < Tt; t++) {
        const __half* hin = g_hh[t & 1];
        __half* hout = g_hh[(t & 1) ^ 1];
        chain_step(t, ca, m0a, cx, c0, sb, maskS, hin, hout, Hseq, isin,
                   br_, bz_, bn_, hregA, tid, lane, wm, wn, ccl0, bl_row, bl_koff);
        chain_step(t, cb, m0b, cx, c0, sb, maskS, hin, hout, Hseq, isin,
                   br_, bz_, bn_, hregB, tid, lane, wm, wn, ccl0, bl_row, bl_koff);
    }
}

// --------------------------- LayerNorm + residual ----------------------------
__global__ void __launch_bounds__(256) ln_kernel(const float* __restrict__ Hseq,
                                                 const float* __restrict__ x,
                                                 const float* __restrict__ gg,
                                                 const float* __restrict__ bbta,
                                                 const float* __restrict__ resg,
                                                 float* __restrict__ Y) {
    const int row = blockIdx.x;
    const float* hp = Hseq + (size_t)row * Hh;
    const int c = threadIdx.x * 4;
    float4 v = *(const float4*)(hp + c);
    float s  = v.x + v.y + v.z + v.w;
    float ss = v.x * v.x + v.y * v.y + v.z * v.z + v.w * v.w;
#pragma unroll
    for (int o = 16; o > 0; o >>= 1) {
        s  += __shfl_xor_sync(0xffffffff, s,  o);
        ss += __shfl_xor_sync(0xffffffff, ss, o);
    }
    __shared__ float smw[8], sm2[8];
    const int w = threadIdx.x >> 5, l = threadIdx.x & 31;
    if (l == 0) { smw[w] = s; sm2[w] = ss; }
    __syncthreads();
    if (threadIdx.x == 0) {
        float a = 0.0f, b2 = 0.0f;
#pragma unroll
        for (int i = 0; i < 8; i++) { a += smw[i]; b2 += sm2[i]; }
        smw[0] = a; sm2[0] = b2;
    }
    __syncthreads();
    const float mu  = smw[0] * (1.0f / Hh);
    const float var = sm2[0] * (1.0f / Hh) - mu * mu;
    const float inv = rsqrtf(var + 1e-5f);
    const float4 xv = *(const float4*)(x + (size_t)row * Dd + c);
    const float4 gv = *(const float4*)(gg + c);
    const float4 bv = *(const float4*)(bbta + c);
    const float4 rv = *(const float4*)(resg + c);
    float4 y;
    y.x = (v.x - mu) * inv * gv.x + bv.x + xv.x * (1.0f / (1.0f + __expf(-rv.x)));
    y.y = (v.y - mu) * inv * gv.y + bv.y + xv.y * (1.0f / (1.0f + __expf(-rv.y)));
    y.z = (v.z - mu) * inv * gv.z + bv.z + xv.z * (1.0f / (1.0f + __expf(-rv.z)));
    y.w = (v.w - mu) * inv * gv.w + bv.w + xv.w * (1.0f / (1.0f + __expf(-rv.w)));
    *(float4*)(Y + (size_t)row * Hh + c) = y;
}

// ---------------------------------------------------------------------------
extern "C" void kernel_launch(void* const* d_in, const int* in_sizes, int n_in,
                              void* d_out, int out_size) {
    const float* x    = (const float*)d_in[0];
    const float* hx   = (const float*)d_in[1];
    const void*  isin =               d_in[2];
    const float* Wih  = (const float*)d_in[3];
    const float* Whh  = (const float*)d_in[4];
    const float* bih  = (const float*)d_in[5];
    const float* bhh  = (const float*)d_in[6];
    const float* lng  = (const float*)d_in[7];
    const float* lnb  = (const float*)d_in[8];
    const float* rg   = (const float*)d_in[9];

    float* Y = (float*)d_out;
    float* Hseq;
    if ((size_t)out_size >= 2 * BTH) {
        Hseq = Y + BTH;
    } else {
        void* p = nullptr;
        cudaGetSymbolAddress(&p, g_hseq_fallback);
        Hseq = (float*)p;
    }

    cudaFuncSetAttribute(gi_gemm, cudaFuncAttributeMaxDynamicSharedMemorySize, GI_SMEM);
    cudaFuncSetAttribute(scan_all, cudaFuncAttributeMaxDynamicSharedMemorySize, PS_SMEM);

    prepA<<<6145, 256>>>(Whh, Wih);                                    // 0 (+ flag reset)
    prepB<<<33025, 256>>>(x, hx, (const unsigned char*)isin);          // 1 (+ mask detect)
    gi_gemm<<<dim3(G3 / 128, BTr / 128), 256, GI_SMEM>>>(bih);         // 2
    scan_all<<<dim3(64, 2), 256, PS_SMEM>>>(bhh, hx, isin, Hseq);      // 3  <- profiled
    ln_kernel<<<BTr, 256>>>(Hseq, x, lng, lnb, rg, Y);                 // 4
}

// round 15
// speedup vs baseline: 1.2607x; 1.2607x over previous
#include <cuda_runtime.h>
#include <cuda_fp16.h>
#include <cstdint>
#include <cstddef>

#define Bb 256
#define Tt 128
#define Dd 1024
#define Hh 1024
#define BTr (Bb*Tt)            // 32768
#define G3  (3*Hh)             // 3072
#define BTH ((size_t)BTr*Hh)

// ------------------------- device scratch (no mallocs) ----------------------
__device__ float g_gi[(size_t)BTr * G3];                  // 402 MB
__device__ float g_hseq_fallback[BTH];                    // 128 MB
__device__ int   g_mask_mode;
__device__ unsigned int g_flag[2][Tt][8];                 // dataflow flags (to 8)
__device__ __align__(16) __half g_whh[(size_t)G3 * Hh];   // W_hh fp16
__device__ __align__(16) __half g_wih[(size_t)G3 * Dd];   // W_ih fp16
__device__ __align__(16) __half g_x[(size_t)BTr * Dd];    // x fp16
__device__ __align__(16) __half g_hh[2][(size_t)Bb * Hh]; // h ping-pong fp16

// ------------------------------ PTX helpers (base sm_103 safe) ---------------
__device__ __forceinline__ uint32_t smem_u32(const void* p) {
    uint32_t a;
    asm("{ .reg .u64 t; cvta.to.shared.u64 t, %1; cvt.u32.u64 %0, t; }"
        : "=r"(a) : "l"(p));
    return a;
}
__device__ __forceinline__ void cp16(uint32_t dst, const void* src) {
    asm volatile("cp.async.cg.shared.global [%0], [%1], 16;"
                 :: "r"(dst), "l"(src) : "memory");
}
#define CP_COMMIT() asm volatile("cp.async.commit_group;" ::: "memory")
#define CP_WAIT(n)  asm volatile("cp.async.wait_group %0;" :: "n"(n) : "memory")

__device__ __forceinline__ void ldsm_x4(uint32_t* r, uint32_t addr) {
    asm volatile("ldmatrix.sync.aligned.m8n8.x4.shared.b16 {%0,%1,%2,%3}, [%4];"
                 : "=r"(r[0]), "=r"(r[1]), "=r"(r[2]), "=r"(r[3]) : "r"(addr));
}
__device__ __forceinline__ void ldsm_x2(uint32_t* r, uint32_t addr) {
    asm volatile("ldmatrix.sync.aligned.m8n8.x2.shared.b16 {%0,%1}, [%2];"
                 : "=r"(r[0]), "=r"(r[1]) : "r"(addr));
}
__device__ __forceinline__ void mma16816h(float* d, const uint32_t* a, const uint32_t* b) {
    asm volatile("mma.sync.aligned.m16n8k16.row.col.f32.f16.f16.f32 "
                 "{%0,%1,%2,%3}, {%4,%5,%6,%7}, {%8,%9}, {%0,%1,%2,%3};"
                 : "+f"(d[0]), "+f"(d[1]), "+f"(d[2]), "+f"(d[3])
                 : "r"(a[0]), "r"(a[1]), "r"(a[2]), "r"(a[3]), "r"(b[0]), "r"(b[1]));
}
__device__ __forceinline__ uint32_t pack2h(__half a, __half b) {
    return ((uint32_t)__half_as_ushort(b) << 16) | __half_as_ushort(a);
}
__device__ __forceinline__ unsigned int ld_acq(const unsigned int* p) {
    unsigned int v;
    asm volatile("ld.acquire.gpu.global.u32 %0, [%1];" : "=r"(v) : "l"(p) : "memory");
    return v;
}
__device__ __forceinline__ void red_release(unsigned int* p, unsigned int v) {
    asm volatile("red.release.gpu.global.add.u32 [%0], %1;" :: "l"(p), "r"(v) : "memory");
}
__device__ __forceinline__ void wait_n(const unsigned int* f, unsigned int n) {
    while (ld_acq(f) < n) __nanosleep(20);
}
// fast transcendentals (MUFU-only, error ~2^-22: negligible vs 3.4e-4 budget)
__device__ __forceinline__ float fast_ex2(float x) {
    float y; asm("ex2.approx.f32 %0, %1;" : "=f"(y) : "f"(x)); return y;
}
__device__ __forceinline__ float fast_rcp(float x) {
    float y; asm("rcp.approx.f32 %0, %1;" : "=f"(y) : "f"(x)); return y;
}
__device__ __forceinline__ float fast_sigmoid(float x) {
    return fast_rcp(1.0f + fast_ex2(x * -1.4426950408889634f));
}
__device__ __forceinline__ float fast_tanh(float x) {
    // tanh(x) = 2*sigmoid(2x) - 1
    return fmaf(2.0f, fast_rcp(1.0f + fast_ex2(x * -2.8853900817779268f)), -1.0f);
}

// --------------------------- mask dtype handling ------------------------------
__device__ __forceinline__ float mask_of(const void* p, int b, int t) {
    int idx = b * Tt + t;
    int mode = g_mask_mode;
    bool ii;
    if (mode == 2)      ii = ((const float*)p)[idx] != 0.0f;
    else if (mode == 1) ii = ((const unsigned char*)p)[idx] != 0;
    else                ii = ((const int*)p)[idx] != 0;
    return ii ? 0.0f : 1.0f;
}

// --------------------- prep: fp32 -> fp16 (+ folded housekeeping) ------------
__device__ __forceinline__ void to_h4(const float4* src, __half* dst, size_t i) {
    float4 v = src[i];
    ((uint2*)dst)[i] = make_uint2(pack2h(__float2half(v.x), __float2half(v.y)),
                                  pack2h(__float2half(v.z), __float2half(v.w)));
}
// prepA: W_hh [0,3072) + W_ih [3072,6144) + block 6144 = reset flags
__global__ void __launch_bounds__(256) prepA(const float* __restrict__ Whh,
                                             const float* __restrict__ Wih) {
    int b = blockIdx.x;
    if (b < 3072) to_h4((const float4*)Whh, g_whh, (size_t)b * 256 + threadIdx.x);
    else if (b < 6144) to_h4((const float4*)Wih, g_wih, (size_t)(b - 3072) * 256 + threadIdx.x);
    else {
        unsigned int* f = &g_flag[0][0][0];
        for (int i = threadIdx.x; i < 2 * Tt * 8; i += 256) f[i] = 0u;
    }
}
// prepB: x [0,32768) + hx [32768,33024) + block 33024 = detect mask dtype
__global__ void __launch_bounds__(256) prepB(const float* __restrict__ x,
                                             const float* __restrict__ hx,
                                             const unsigned char* __restrict__ isin) {
    int b = blockIdx.x;
    if (b < 32768) { to_h4((const float4*)x, g_x, (size_t)b * 256 + threadIdx.x); return; }
    if (b < 33024) {
        to_h4((const float4*)hx, g_hh[0], (size_t)(b - 32768) * 256 + threadIdx.x);
        return;
    }
    __shared__ int s_off, s_gt1;
    if (threadIdx.x == 0) { s_off = 0; s_gt1 = 0; }
    __syncthreads();
    int f_off = 0, f_gt1 = 0;
    for (int i = threadIdx.x; i < 4096; i += 256) {
        unsigned char v = isin[i];
        if ((i & 3) != 0 && v) f_off = 1;
        if (v > 1) f_gt1 = 1;
    }
    if (f_off) atomicOr(&s_off, 1);
    if (f_gt1) atomicOr(&s_gt1, 1);
    __syncthreads();
    if (threadIdx.x == 0) g_mask_mode = s_gt1 ? 2 : (s_off ? 1 : 0);
}

// ------- gi = x @ W_ih^T + b_ih  (fp16, KC=64, 3-stage, 1 sync/chunk) --------
#define GI_KC 64
#define GI_NCH 16
#define GI_PITCH 144                    // 64 fp16 = 128B + 16 pad
#define GI_AB (128 * GI_PITCH)          // 18432
#define GI_STAGE (2 * GI_AB)            // 36864: [A|B]
#define GI_SMEM (3 * GI_STAGE)          // 110592 (x2 blocks/SM = 221KB)

__global__ void __launch_bounds__(256, 2) gi_gemm(const float* __restrict__ bias) {
    extern __shared__ char sm[];
    const uint32_t sb = smem_u32(sm);
    const int tid = threadIdx.x, lane = tid & 31, wid = tid >> 5;
    const int wm = wid >> 2, wn = wid & 3;
    const int n0 = blockIdx.x * 128, m0 = blockIdx.y * 128;

    float acc[4][4][4];
#pragma unroll
    for (int i = 0; i < 4; i++)
#pragma unroll
        for (int j = 0; j < 4; j++)
#pragma unroll
            for (int k = 0; k < 4; k++) acc[i][j][k] = 0.0f;

#define GI_ISSUE(ch) do {                                                        \
    const int _c = (ch);                                                         \
    const uint32_t base = sb + (_c % 3) * GI_STAGE;                              \
    _Pragma("unroll")                                                            \
    for (int it = 0; it < 4; it++) {                                             \
        int i = tid + it * 256, r = i >> 3, q = i & 7;                           \
        cp16(base + r * GI_PITCH + q * 16,                                       \
             g_x + (size_t)(m0 + r) * Dd + _c * GI_KC + q * 8);                  \
    }                                                                            \
    _Pragma("unroll")                                                            \
    for (int it = 0; it < 4; it++) {                                             \
        int i = tid + it * 256, r = i >> 3, q = i & 7;                           \
        cp16(base + GI_AB + r * GI_PITCH + q * 16,                               \
             g_wih + (size_t)(n0 + r) * Dd + _c * GI_KC + q * 8);                \
    }                                                                            \
    CP_COMMIT(); } while (0)

    // fused B-ldsm lane mapping: row = (l>>4)*8 + (l&7), k-half = (l>>3)&1
    const int bl_row = ((lane >> 4) << 3) + (lane & 7);
    const int bl_koff = ((lane >> 3) & 1) * 16;

    GI_ISSUE(0);
    GI_ISSUE(1);
    for (int ch = 0; ch < GI_NCH; ch++) {
        if (ch == GI_NCH - 1) { CP_WAIT(0); } else { CP_WAIT(1); }
        __syncthreads();
        if (ch + 2 < GI_NCH) GI_ISSUE(ch + 2);     // writes stage (ch+2)%3, safe
        const uint32_t base = sb + (ch % 3) * GI_STAGE;
        const uint32_t aS = base, bS = base + GI_AB;
#pragma unroll
        for (int ks = 0; ks < 4; ks++) {
            uint32_t ah[4][4], bh[4][2];
#pragma unroll
            for (int ma = 0; ma < 4; ma++)
                ldsm_x4(ah[ma], aS + (wm * 64 + ma * 16 + (lane & 15)) * GI_PITCH
                                    + ks * 32 + (lane >> 4) * 16);
#pragma unroll
            for (int np = 0; np < 2; np++)          // na pairs {0,1},{2,3} in one x4
                ldsm_x4(&bh[np * 2][0],
                        bS + (wn * 32 + np * 16 + bl_row) * GI_PITCH
                           + ks * 32 + bl_koff);
#pragma unroll
            for (int ma = 0; ma < 4; ma++)
#pragma unroll
                for (int na = 0; na < 4; na++) mma16816h(acc[ma][na], ah[ma], bh[na]);
        }
    }
#pragma unroll
    for (int ma = 0; ma < 4; ma++) {
        const int row = m0 + wm * 64 + ma * 16 + (lane >> 2);
#pragma unroll
        for (int na = 0; na < 4; na++) {
            const int col = n0 + wn * 32 + na * 8 + (lane & 3) * 2;
            const float b0 = bias[col], b1 = bias[col + 1];
            float* p = g_gi + (size_t)row * G3 + col;
            *(float2*)p = make_float2(acc[ma][na][0] + b0, acc[ma][na][1] + b1);
            *(float2*)(p + 8 * (size_t)G3) =
                make_float2(acc[ma][na][2] + b0, acc[ma][na][3] + b1);
        }
    }
}

// ------- persistent scan: fp16, W resident, KC=128, 3-stage A, 1 sync/chunk --
#define KC 128
#define NCH 8
#define A_PITCH 272                         // 128 fp16 = 256B + 16 pad
#define A_BUF (128 * A_PITCH)               // 34816
#define SM_W (3 * A_BUF)                    // 104448
#define W_PITCH 2064                        // 1024 fp16 = 2048B + 16 pad
#define W_PART (48 * W_PITCH)               // 99072
#define SM_MASK (SM_W + W_PART)             // 203520
#define PS_SMEM (SM_MASK + 640)             // 204160

__global__ void __launch_bounds__(256)
scan_all(const float* __restrict__ bhh, const float* __restrict__ hx,
         const void* __restrict__ isin, float* __restrict__ Hseq) {
    extern __shared__ char sm[];
    const uint32_t sb = smem_u32(sm);
    float* maskS = (float*)(sm + SM_MASK);
    const int tid = threadIdx.x, lane = tid & 31, wid = tid >> 5;
    const int wm = wid >> 1, wn = wid & 1;           // 4 x 2 warps
    const int cx = blockIdx.x, grp = blockIdx.y;
    const int c0 = cx * 16, m0 = grp * 128;

    // ---- one-time: load W slice into resident smem (remapped rows) ----
#pragma unroll 8
    for (int it = 0; it < 24; it++) {
        int i = tid + it * 256;                      // 0..6143
        int rs = i >> 7, q = i & 127;
        int g = rs >> 4, ccl = rs & 15;
        int rr = (ccl >> 3) * 24 + g * 8 + (ccl & 7);
        cp16(sb + SM_W + rr * W_PITCH + q * 16,
             g_whh + (size_t)(g * Hh + c0 + ccl) * Hh + q * 8);
    }
    CP_COMMIT();

#define PS_ISSUE_A(cc, hin) do {                                                 \
    const uint32_t base = sb + ((cc) % 3) * A_BUF;                               \
    _Pragma("unroll")                                                            \
    for (int it = 0; it < 8; it++) {                                             \
        int i = tid + it * 256, r = i >> 4, q = i & 15;                          \
        cp16(base + r * A_PITCH + q * 16,                                        \
             (hin) + (size_t)(m0 + r) * Hh + (cc) * KC + q * 8);                 \
    }                                                                            \
    CP_COMMIT(); } while (0)

    // per-thread invariants for the register epilogue
    const int ccl0 = wn * 8 + (lane & 3) * 2;        // local col (0..15)
    const int bl_row = ((lane >> 4) << 3) + (lane & 7);   // fused B-ldsm lane map
    const int bl_koff = ((lane >> 3) & 1) * 16;
    float br_[2], bz_[2], bn_[2];
#pragma unroll
    for (int j = 0; j < 2; j++) {
        br_[j] = bhh[c0 + ccl0 + j];
        bz_[j] = bhh[Hh + c0 + ccl0 + j];
        bn_[j] = bhh[2 * Hh + c0 + ccl0 + j];
    }
    float hreg[2][2][2];
#pragma unroll
    for (int ma = 0; ma < 2; ma++)
#pragma unroll
        for (int rh = 0; rh < 2; rh++) {
            const int brow = m0 + wm * 32 + ma * 16 + (lane >> 2) + rh * 8;
            hreg[ma][rh][0] = hx[(size_t)brow * Hh + c0 + ccl0];
            hreg[ma][rh][1] = hx[(size_t)brow * Hh + c0 + ccl0 + 1];
        }

    for (int t = 0; t < Tt; t++) {
        const __half* hin = g_hh[t & 1];
        __half* hout = g_hh[(t & 1) ^ 1];

        // gi registers (h-independent): load before any dataflow wait
        float2 gir[3][2][2];
#pragma unroll
        for (int ma = 0; ma < 2; ma++)
#pragma unroll
            for (int rh = 0; rh < 2; rh++) {
                const size_t rbase =
                    ((size_t)(m0 + wm * 32 + ma * 16 + (lane >> 2) + rh * 8) * Tt + t)
                    * G3 + c0 + ccl0;
#pragma unroll
                for (int g = 0; g < 3; g++)
                    gir[g][ma][rh] = *(const float2*)(g_gi + rbase + g * Hh);
            }

        if (tid < 128) maskS[tid] = mask_of(isin, m0 + tid, t);

        // prologue: chunks 0,1 (distance-2 pipeline)
        if (t > 0) wait_n(&g_flag[grp][t - 1][0], 8);
        PS_ISSUE_A(0, hin);
        if (t > 0) wait_n(&g_flag[grp][t - 1][1], 8);
        PS_ISSUE_A(1, hin);

        float acc[2][3][4];
#pragma unroll
        for (int i = 0; i < 2; i++)
#pragma unroll
            for (int j = 0; j < 3; j++)
#pragma unroll
                for (int k = 0; k < 4; k++) acc[i][j][k] = 0.0f;

        for (int ch = 0; ch < NCH; ch++) {
            if (ch == NCH - 1) { CP_WAIT(0); } else { CP_WAIT(1); }
            __syncthreads();
            if (ch + 2 < NCH) {
                if (t > 0) wait_n(&g_flag[grp][t - 1][ch + 2], 8);
                PS_ISSUE_A(ch + 2, hin);      // writes stage (ch+2)%3, safe
            }
            const uint32_t abase = sb + (ch % 3) * A_BUF;
            const uint32_t wS = sb + SM_W + ch * 256;   // k offset: ch*128 el *2B
#pragma unroll
            for (int ks = 0; ks < 8; ks++) {
                uint32_t ah[2][4], bh[3][2];
#pragma unroll
                for (int ma = 0; ma < 2; ma++)
                    ldsm_x4(ah[ma], abase + (wm * 32 + ma * 16 + (lane & 15)) * A_PITCH
                                          + ks * 32 + (lane >> 4) * 16);
                // na pair {0,1} fused in one x4; na=2 via x2
                ldsm_x4(&bh[0][0], wS + (wn * 24 + bl_row) * W_PITCH
                                      + ks * 32 + bl_koff);
                {
                    int l = lane & 15;
                    ldsm_x2(bh[2], wS + (wn * 24 + 16 + (l & 7)) * W_PITCH
                                      + ks * 32 + (l >> 3) * 16);
                }
#pragma unroll
                for (int ma = 0; ma < 2; ma++)
#pragma unroll
                    for (int na = 0; na < 3; na++) mma16816h(acc[ma][na], ah[ma], bh[na]);
            }
        }

        // --------- register epilogue: na==gate, cols ccl0..ccl0+1 ---------
#pragma unroll
        for (int ma = 0; ma < 2; ma++)
#pragma unroll
            for (int rh = 0; rh < 2; rh++) {
                const int lr = wm * 32 + ma * 16 + (lane >> 2) + rh * 8;
                const int brow = m0 + lr;
                const float m = maskS[lr];
                float hv[2];
#pragma unroll
                for (int j = 0; j < 2; j++) {
                    const int k = rh * 2 + j;
                    const float hrv = m * acc[ma][0][k] + br_[j];
                    const float hzv = m * acc[ma][1][k] + bz_[j];
                    const float hnv = m * acc[ma][2][k] + bn_[j];
                    const float ir  = j ? gir[0][ma][rh].y : gir[0][ma][rh].x;
                    const float iz  = j ? gir[1][ma][rh].y : gir[1][ma][rh].x;
                    const float inn = j ? gir[2][ma][rh].y : gir[2][ma][rh].x;
                    const float rg = fast_sigmoid(ir + hrv);
                    const float z  = fast_sigmoid(iz + hzv);
                    const float n  = fast_tanh(inn + rg * hnv);
                    hv[j] = (1.0f - z) * n + z * (hreg[ma][rh][j] * m);
                    hreg[ma][rh][j] = hv[j];
                }
                *(float2*)(Hseq + ((size_t)brow * Tt + t) * Hh + c0 + ccl0) =
                    make_float2(hv[0], hv[1]);
                *(uint32_t*)(hout + (size_t)brow * Hh + c0 + ccl0) =
                    pack2h(__float2half(hv[0]), __float2half(hv[1]));
            }
        // release: bar.sync orders all threads' writes before tid0's release
        __syncthreads();
        if (tid == 0 && t + 1 < Tt) red_release(&g_flag[grp][t][cx >> 3], 1u);
    }
}

// --------------------------- LayerNorm + residual ----------------------------
__global__ void __launch_bounds__(256) ln_kernel(const float* __restrict__ Hseq,
                                                 const float* __restrict__ x,
                                                 const float* __restrict__ gg,
                                                 const float* __restrict__ bbta,
                                                 const float* __restrict__ resg,
                                                 float* __restrict__ Y) {
    const int row = blockIdx.x;
    const float* hp = Hseq + (size_t)row * Hh;
    const int c = threadIdx.x * 4;
    float4 v = *(const float4*)(hp + c);
    float s  = v.x + v.y + v.z + v.w;
    float ss = v.x * v.x + v.y * v.y + v.z * v.z + v.w * v.w;
#pragma unroll
    for (int o = 16; o > 0; o >>= 1) {
        s  += __shfl_xor_sync(0xffffffff, s,  o);
        ss += __shfl_xor_sync(0xffffffff, ss, o);
    }
    __shared__ float smw[8], sm2[8];
    const int w = threadIdx.x >> 5, l = threadIdx.x & 31;
    if (l == 0) { smw[w] = s; sm2[w] = ss; }
    __syncthreads();
    if (threadIdx.x == 0) {
        float a = 0.0f, b2 = 0.0f;
#pragma unroll
        for (int i = 0; i < 8; i++) { a += smw[i]; b2 += sm2[i]; }
        smw[0] = a; sm2[0] = b2;
    }
    __syncthreads();
    const float mu  = smw[0] * (1.0f / Hh);
    const float var = sm2[0] * (1.0f / Hh) - mu * mu;
    const float inv = rsqrtf(var + 1e-5f);
    const float4 xv = *(const float4*)(x + (size_t)row * Dd + c);
    const float4 gv = *(const float4*)(gg + c);
    const float4 bv = *(const float4*)(bbta + c);
    const float4 rv = *(const float4*)(resg + c);
    float4 y;
    y.x = (v.x - mu) * inv * gv.x + bv.x + xv.x * fast_sigmoid(rv.x);
    y.y = (v.y - mu) * inv * gv.y + bv.y + xv.y * fast_sigmoid(rv.y);
    y.z = (v.z - mu) * inv * gv.z + bv.z + xv.z * fast_sigmoid(rv.z);
    y.w = (v.w - mu) * inv * gv.w + bv.w + xv.w * fast_sigmoid(rv.w);
    *(float4*)(Y + (size_t)row * Hh + c) = y;
}

// ---------------------------------------------------------------------------
extern "C" void kernel_launch(void* const* d_in, const int* in_sizes, int n_in,
                              void* d_out, int out_size) {
    const float* x    = (const float*)d_in[0];
    const float* hx   = (const float*)d_in[1];
    const void*  isin =               d_in[2];
    const float* Wih  = (const float*)d_in[3];
    const float* Whh  = (const float*)d_in[4];
    const float* bih  = (const float*)d_in[5];
    const float* bhh  = (const float*)d_in[6];
    const float* lng  = (const float*)d_in[7];
    const float* lnb  = (const float*)d_in[8];
    const float* rg   = (const float*)d_in[9];

    float* Y = (float*)d_out;
    float* Hseq;
    if ((size_t)out_size >= 2 * BTH) {
        Hseq = Y + BTH;
    } else {
        void* p = nullptr;
        cudaGetSymbolAddress(&p, g_hseq_fallback);
        Hseq = (float*)p;
    }

    cudaFuncSetAttribute(gi_gemm, cudaFuncAttributeMaxDynamicSharedMemorySize, GI_SMEM);
    cudaFuncSetAttribute(scan_all, cudaFuncAttributeMaxDynamicSharedMemorySize, PS_SMEM);

    prepA<<<6145, 256>>>(Whh, Wih);                                    // 0 (+ flag reset)
    prepB<<<33025, 256>>>(x, hx, (const unsigned char*)isin);          // 1 (+ mask detect)
    gi_gemm<<<dim3(G3 / 128, BTr / 128), 256, GI_SMEM>>>(bih);         // 2
    scan_all<<<dim3(64, 2), 256, PS_SMEM>>>(bhh, hx, isin, Hseq);      // 3  <- profiled
    ln_kernel<<<BTr, 256>>>(Hseq, x, lng, lnb, rg, Y);                 // 4
}